// round 1
// baseline (speedup 1.0000x reference)
#include <cuda_runtime.h>
#include <math.h>

#define D 128
#define NMAX 50048
#define EMAX 800000
#define GMAX 64

// ---- scratch (static device globals; no runtime allocation) ----
__device__ float g_dinv[NMAX];
__device__ int   g_deg[NMAX];
__device__ int   g_rowptr[NMAX + 1];
__device__ int   g_cursor[NMAX];
__device__ int   g_csr[EMAX];
__device__ float g_hw[NMAX * D];   // GEMM output (pre-aggregation)
__device__ float g_h[NMAX * D];    // layer output
__device__ float g_pool[GMAX * D];

// ------------------------------------------------------------------
__global__ void k_init(int n, int gtot) {
    int i = blockIdx.x * blockDim.x + threadIdx.x;
    if (i < n) { g_deg[i] = 0; g_cursor[i] = 0; }
    if (i < gtot) g_pool[i] = 0.0f;
}

__global__ void k_count(const int* __restrict__ dst, int e) {
    int i = blockIdx.x * blockDim.x + threadIdx.x;
    if (i < e) atomicAdd(&g_deg[dst[i]], 1);
}

__global__ void k_dinv(int n) {
    int i = blockIdx.x * blockDim.x + threadIdx.x;
    if (i < n) g_dinv[i] = rsqrtf((float)(g_deg[i] + 1));  // +1 self loop
}

// exclusive scan of g_deg -> g_rowptr, single block of 1024 threads
__global__ void k_scan(int n) {
    __shared__ int sums[1024];
    const int t = threadIdx.x;
    const int chunk = (n + 1023) / 1024;
    int beg = t * chunk;
    int end = beg + chunk; if (end > n) end = n;
    int s = 0;
    for (int i = beg; i < end; i++) s += g_deg[i];
    sums[t] = s;
    __syncthreads();
    // Hillis-Steele inclusive scan
    for (int off = 1; off < 1024; off <<= 1) {
        int v = (t >= off) ? sums[t - off] : 0;
        __syncthreads();
        sums[t] += v;
        __syncthreads();
    }
    int excl = (t == 0) ? 0 : sums[t - 1];
    for (int i = beg; i < end; i++) { g_rowptr[i] = excl; excl += g_deg[i]; }
    if (t == 1023) g_rowptr[n] = sums[1023];
}

__global__ void k_fill(const int* __restrict__ src, const int* __restrict__ dst, int e) {
    int i = blockIdx.x * blockDim.x + threadIdx.x;
    if (i < e) {
        int d = dst[i];
        int p = atomicAdd(&g_cursor[d], 1);
        g_csr[g_rowptr[d] + p] = src[i];
    }
}

// ------------------------------------------------------------------
// C[n,128] = A[n,128] @ W[128,128], fp32. BM=64, BN=128, BK=32, 256 threads,
// each thread computes an 8x4 micro-tile.
__global__ __launch_bounds__(256) void k_gemm(const float* __restrict__ A,
                                              const float* __restrict__ W,
                                              float* __restrict__ C, int n) {
    __shared__ float As[64 * 32];
    __shared__ float Bs[32 * 128];
    const int tid = threadIdx.x;
    const int tx = tid & 31;   // col group (x4)
    const int ty = tid >> 5;   // row group (x8)
    const int row0 = blockIdx.x * 64;
    float acc[8][4];
#pragma unroll
    for (int r = 0; r < 8; r++)
#pragma unroll
        for (int c = 0; c < 4; c++) acc[r][c] = 0.0f;

    for (int k0 = 0; k0 < 128; k0 += 32) {
        // load A tile: 64x32 = 512 float4, 2 per thread
#pragma unroll
        for (int i = 0; i < 2; i++) {
            int idx = tid + i * 256;
            int r = idx >> 3;
            int c = (idx & 7) << 2;
            float4 v = make_float4(0.f, 0.f, 0.f, 0.f);
            if (row0 + r < n) v = *(const float4*)(A + (size_t)(row0 + r) * 128 + k0 + c);
            *(float4*)(As + r * 32 + c) = v;
        }
        // load W tile: 32x128 = 1024 float4, 4 per thread
#pragma unroll
        for (int i = 0; i < 4; i++) {
            int idx = tid + i * 256;
            int r = idx >> 5;
            int c = (idx & 31) << 2;
            *(float4*)(Bs + r * 128 + c) = *(const float4*)(W + (size_t)(k0 + r) * 128 + c);
        }
        __syncthreads();
#pragma unroll
        for (int k = 0; k < 32; k++) {
            float4 bv = *(const float4*)(Bs + k * 128 + tx * 4);
#pragma unroll
            for (int r = 0; r < 8; r++) {
                float a = As[(ty * 8 + r) * 32 + k];
                acc[r][0] = fmaf(a, bv.x, acc[r][0]);
                acc[r][1] = fmaf(a, bv.y, acc[r][1]);
                acc[r][2] = fmaf(a, bv.z, acc[r][2]);
                acc[r][3] = fmaf(a, bv.w, acc[r][3]);
            }
        }
        __syncthreads();
    }
#pragma unroll
    for (int r = 0; r < 8; r++) {
        int row = row0 + ty * 8 + r;
        if (row < n)
            *(float4*)(C + (size_t)row * 128 + tx * 4) =
                make_float4(acc[r][0], acc[r][1], acc[r][2], acc[r][3]);
    }
}

// ------------------------------------------------------------------
// One warp per node: CSR gather-accumulate + self loop, then bias + LayerNorm
// + ReLU fused, write to g_h.
__global__ __launch_bounds__(256) void k_agg(const float* __restrict__ hw,
                                             const float* __restrict__ bias,
                                             const float* __restrict__ gamma,
                                             const float* __restrict__ beta, int n) {
    int node = (blockIdx.x * blockDim.x + threadIdx.x) >> 5;
    int lane = threadIdx.x & 31;
    if (node >= n) return;
    const float4* hv = (const float4*)hw;
    float di = g_dinv[node];
    float4 sv = hv[(size_t)node * 32 + lane];
    float ax = di * sv.x, ay = di * sv.y, az = di * sv.z, aw = di * sv.w;

    int e = g_rowptr[node], end = g_rowptr[node + 1];
    for (; e + 4 <= end; e += 4) {
        int s0 = g_csr[e], s1 = g_csr[e + 1], s2 = g_csr[e + 2], s3 = g_csr[e + 3];
        float w0 = g_dinv[s0], w1 = g_dinv[s1], w2 = g_dinv[s2], w3 = g_dinv[s3];
        float4 v0 = hv[(size_t)s0 * 32 + lane];
        float4 v1 = hv[(size_t)s1 * 32 + lane];
        float4 v2 = hv[(size_t)s2 * 32 + lane];
        float4 v3 = hv[(size_t)s3 * 32 + lane];
        ax = fmaf(w0, v0.x, ax); ay = fmaf(w0, v0.y, ay); az = fmaf(w0, v0.z, az); aw = fmaf(w0, v0.w, aw);
        ax = fmaf(w1, v1.x, ax); ay = fmaf(w1, v1.y, ay); az = fmaf(w1, v1.z, az); aw = fmaf(w1, v1.w, aw);
        ax = fmaf(w2, v2.x, ax); ay = fmaf(w2, v2.y, ay); az = fmaf(w2, v2.z, az); aw = fmaf(w2, v2.w, aw);
        ax = fmaf(w3, v3.x, ax); ay = fmaf(w3, v3.y, ay); az = fmaf(w3, v3.z, az); aw = fmaf(w3, v3.w, aw);
    }
    for (; e < end; e++) {
        int s = g_csr[e];
        float w = g_dinv[s];
        float4 v = hv[(size_t)s * 32 + lane];
        ax = fmaf(w, v.x, ax); ay = fmaf(w, v.y, ay); az = fmaf(w, v.z, az); aw = fmaf(w, v.w, aw);
    }
    float4 bb = ((const float4*)bias)[lane];
    ax = fmaf(ax, di, bb.x); ay = fmaf(ay, di, bb.y);
    az = fmaf(az, di, bb.z); aw = fmaf(aw, di, bb.w);

    // LayerNorm over 128 via warp reduce
    float s = ax + ay + az + aw;
#pragma unroll
    for (int o = 16; o; o >>= 1) s += __shfl_xor_sync(0xffffffffu, s, o);
    float mean = s * (1.0f / 128.0f);
    float cx = ax - mean, cy = ay - mean, cz = az - mean, cw = aw - mean;
    float v2 = cx * cx + cy * cy + cz * cz + cw * cw;
#pragma unroll
    for (int o = 16; o; o >>= 1) v2 += __shfl_xor_sync(0xffffffffu, v2, o);
    float inv = rsqrtf(v2 * (1.0f / 128.0f) + 1e-5f);
    float4 gg = ((const float4*)gamma)[lane];
    float4 be = ((const float4*)beta)[lane];
    float ox = fmaxf(fmaf(gg.x * cx, inv, be.x), 0.0f);
    float oy = fmaxf(fmaf(gg.y * cy, inv, be.y), 0.0f);
    float oz = fmaxf(fmaf(gg.z * cz, inv, be.z), 0.0f);
    float ow = fmaxf(fmaf(gg.w * cw, inv, be.w), 0.0f);
    ((float4*)g_h)[(size_t)node * 32 + lane] = make_float4(ox, oy, oz, ow);
}

// ------------------------------------------------------------------
// Pooling: warp handles CHUNK consecutive nodes; batch is sorted, so flush
// atomics only on graph-id change.
#define PCHUNK 50
__global__ __launch_bounds__(256) void k_pool(const int* __restrict__ batch, int n) {
    int warp = (blockIdx.x * blockDim.x + threadIdx.x) >> 5;
    int lane = threadIdx.x & 31;
    int beg = warp * PCHUNK;
    if (beg >= n) return;
    int end = beg + PCHUNK; if (end > n) end = n;
    const float4* hv = (const float4*)g_h;
    float ax = 0.f, ay = 0.f, az = 0.f, aw = 0.f;
    int cur = batch[beg];
    for (int i = beg; i < end; i++) {
        int b = batch[i];
        if (b != cur) {
            float* p = g_pool + (size_t)cur * D + lane * 4;
            atomicAdd(p + 0, ax); atomicAdd(p + 1, ay);
            atomicAdd(p + 2, az); atomicAdd(p + 3, aw);
            ax = ay = az = aw = 0.f;
            cur = b;
        }
        float4 v = hv[(size_t)i * 32 + lane];
        ax += v.x; ay += v.y; az += v.z; aw += v.w;
    }
    float* p = g_pool + (size_t)cur * D + lane * 4;
    atomicAdd(p + 0, ax); atomicAdd(p + 1, ay);
    atomicAdd(p + 2, az); atomicAdd(p + 3, aw);
}

__device__ __forceinline__ int lower_bound(const int* a, int n, int v) {
    int lo = 0, hi = n;
    while (lo < hi) { int m = (lo + hi) >> 1; if (a[m] < v) lo = m + 1; else hi = m; }
    return lo;
}

__global__ void k_final(const int* __restrict__ batch, int n, int g, float* __restrict__ out) {
    int i = blockIdx.x * blockDim.x + threadIdx.x;
    if (i >= g * D) return;
    int gi = i / D;
    int cnt = lower_bound(batch, n, gi + 1) - lower_bound(batch, n, gi);
    float c = (float)cnt;
    out[i] = g_pool[i] / fmaxf(c, 1.0f);
}

// ------------------------------------------------------------------
extern "C" void kernel_launch(void* const* d_in, const int* in_sizes, int n_in,
                              void* d_out, int out_size) {
    const float* x      = (const float*)d_in[0];
    const int*   ei     = (const int*)d_in[1];
    const int*   batch  = (const int*)d_in[2];
    const float* Ws     = (const float*)d_in[3];
    const float* bs     = (const float*)d_in[4];
    const float* gammas = (const float*)d_in[5];
    const float* betas  = (const float*)d_in[6];
    float* out = (float*)d_out;

    const int n = in_sizes[0] / D;
    const int e = in_sizes[1] / 2;
    const int L = in_sizes[3] / (D * D);
    const int g = out_size / D;
    const int* src = ei;
    const int* dst = ei + e;

    float* hptr = nullptr;
    float* hwptr = nullptr;
    cudaGetSymbolAddress((void**)&hptr, g_h);
    cudaGetSymbolAddress((void**)&hwptr, g_hw);

    int initN = n > g * D ? n : g * D;
    k_init<<<(initN + 255) / 256, 256>>>(n, g * D);
    k_count<<<(e + 255) / 256, 256>>>(dst, e);
    k_dinv<<<(n + 255) / 256, 256>>>(n);
    k_scan<<<1, 1024>>>(n);
    k_fill<<<(e + 255) / 256, 256>>>(src, dst, e);

    for (int l = 0; l < L; l++) {
        const float* A = (l == 0) ? x : hptr;
        k_gemm<<<(n + 63) / 64, 256>>>(A, Ws + (size_t)l * D * D, hwptr, n);
        k_agg<<<((n * 32) + 255) / 256, 256>>>(hwptr, bs + (size_t)l * D,
                                               gammas + (size_t)l * D,
                                               betas + (size_t)l * D, n);
    }

    int pwarps = (n + PCHUNK - 1) / PCHUNK;
    k_pool<<<((pwarps * 32) + 255) / 256, 256>>>(batch, n);
    k_final<<<(g * D + 255) / 256, 256>>>(batch, n, g, out);
}

// round 2
// speedup vs baseline: 1.0982x; 1.0982x over previous
#include <cuda_runtime.h>
#include <math.h>

#define D 128
#define NMAX 50048
#define EMAX 800000
#define GMAX 64

// ---- scratch (static device globals; no runtime allocation) ----
__device__ float g_dinv[NMAX];
__device__ int   g_deg[NMAX];
__device__ int   g_rowptr[NMAX + 1];
__device__ int   g_cursor[NMAX];
__device__ int   g_csr[EMAX];
__device__ int   g_bsum[256];
__device__ int   g_boff[256];
__device__ float g_hw[NMAX * D];   // GEMM output (pre-aggregation)
__device__ float g_h[NMAX * D];    // layer output
__device__ float g_pool[GMAX * D];

// ------------------------------------------------------------------
__global__ void k_init(int n, int gtot) {
    int i = blockIdx.x * blockDim.x + threadIdx.x;
    if (i < n) { g_deg[i] = 0; g_cursor[i] = 0; }
    if (i < gtot) g_pool[i] = 0.0f;
}

__global__ void k_count(const int* __restrict__ dst, int e) {
    int i = blockIdx.x * blockDim.x + threadIdx.x;
    if (i < e) atomicAdd(&g_deg[dst[i]], 1);
}

__global__ void k_dinv(int n) {
    int i = blockIdx.x * blockDim.x + threadIdx.x;
    if (i < n) g_dinv[i] = rsqrtf((float)(g_deg[i] + 1));  // +1 self loop
}

// ---- multi-block exclusive scan of g_deg -> g_rowptr ----
// pass 1: per-block (256 elems) local exclusive scan + block sums
__global__ void k_scan1(int n) {
    __shared__ int sh[256];
    const int t = threadIdx.x;
    const int i = blockIdx.x * 256 + t;
    int v = (i < n) ? g_deg[i] : 0;
    sh[t] = v;
    __syncthreads();
#pragma unroll
    for (int o = 1; o < 256; o <<= 1) {
        int u = (t >= o) ? sh[t - o] : 0;
        __syncthreads();
        sh[t] += u;
        __syncthreads();
    }
    if (i < n) g_rowptr[i] = sh[t] - v;  // local exclusive
    if (t == 255) g_bsum[blockIdx.x] = sh[255];
}

// pass 2: single block scans block sums (nb <= 256 since NMAX <= 65536)
__global__ void k_scan2(int n, int nb) {
    __shared__ int sh[256];
    const int t = threadIdx.x;
    int v = (t < nb) ? g_bsum[t] : 0;
    sh[t] = v;
    __syncthreads();
#pragma unroll
    for (int o = 1; o < 256; o <<= 1) {
        int u = (t >= o) ? sh[t - o] : 0;
        __syncthreads();
        sh[t] += u;
        __syncthreads();
    }
    g_boff[t] = sh[t] - v;  // exclusive block offsets
    if (t == 255) g_rowptr[n] = sh[255];
}

// pass 3: add block offsets
__global__ void k_scan3(int n) {
    const int i = blockIdx.x * 256 + threadIdx.x;
    if (i < n) g_rowptr[i] += g_boff[blockIdx.x];
}

__global__ void k_fill(const int* __restrict__ src, const int* __restrict__ dst, int e) {
    int i = blockIdx.x * blockDim.x + threadIdx.x;
    if (i < e) {
        int d = dst[i];
        int p = atomicAdd(&g_cursor[d], 1);
        g_csr[g_rowptr[d] + p] = src[i];
    }
}

// ------------------------------------------------------------------
// C[n,128] = A[n,128] @ W[128,128], fp32.
// BM=128, BN=128, BK=16, 256 threads (16x16), 8x8 micro-tile per thread.
#define ASTRIDE 132
__global__ __launch_bounds__(256) void k_gemm(const float* __restrict__ A,
                                              const float* __restrict__ W,
                                              float* __restrict__ C, int n) {
    __shared__ float As[16 * ASTRIDE];  // transposed: As[k][m]
    __shared__ float Bs[16 * 128];      // Bs[k][nn]
    const int tid = threadIdx.x;
    const int tx = tid & 15;    // col group (x8)
    const int ty = tid >> 4;    // row group (x8)
    const int row0 = blockIdx.x * 128;

    float acc[8][8];
#pragma unroll
    for (int r = 0; r < 8; r++)
#pragma unroll
        for (int c = 0; c < 8; c++) acc[r][c] = 0.0f;

    for (int k0 = 0; k0 < 128; k0 += 16) {
        // load A tile 128x16 (transposed into As)
#pragma unroll
        for (int i = 0; i < 2; i++) {
            int idx = tid + i * 256;
            int r = idx >> 2;
            int c4 = (idx & 3) << 2;
            float4 v = make_float4(0.f, 0.f, 0.f, 0.f);
            if (row0 + r < n)
                v = *(const float4*)(A + (size_t)(row0 + r) * 128 + k0 + c4);
            As[(c4 + 0) * ASTRIDE + r] = v.x;
            As[(c4 + 1) * ASTRIDE + r] = v.y;
            As[(c4 + 2) * ASTRIDE + r] = v.z;
            As[(c4 + 3) * ASTRIDE + r] = v.w;
        }
        // load W tile 16x128
#pragma unroll
        for (int i = 0; i < 2; i++) {
            int idx = tid + i * 256;
            int r = idx >> 5;
            int c = (idx & 31) << 2;
            *(float4*)(Bs + r * 128 + c) = *(const float4*)(W + (size_t)(k0 + r) * 128 + c);
        }
        __syncthreads();
#pragma unroll
        for (int k = 0; k < 16; k++) {
            float4 a0 = *(const float4*)(As + k * ASTRIDE + ty * 8);
            float4 a1 = *(const float4*)(As + k * ASTRIDE + ty * 8 + 4);
            float4 b0 = *(const float4*)(Bs + k * 128 + tx * 8);
            float4 b1 = *(const float4*)(Bs + k * 128 + tx * 8 + 4);
            float av[8] = {a0.x, a0.y, a0.z, a0.w, a1.x, a1.y, a1.z, a1.w};
            float bv[8] = {b0.x, b0.y, b0.z, b0.w, b1.x, b1.y, b1.z, b1.w};
#pragma unroll
            for (int r = 0; r < 8; r++)
#pragma unroll
                for (int c = 0; c < 8; c++)
                    acc[r][c] = fmaf(av[r], bv[c], acc[r][c]);
        }
        __syncthreads();
    }
#pragma unroll
    for (int r = 0; r < 8; r++) {
        int row = row0 + ty * 8 + r;
        if (row < n) {
            *(float4*)(C + (size_t)row * 128 + tx * 8) =
                make_float4(acc[r][0], acc[r][1], acc[r][2], acc[r][3]);
            *(float4*)(C + (size_t)row * 128 + tx * 8 + 4) =
                make_float4(acc[r][4], acc[r][5], acc[r][6], acc[r][7]);
        }
    }
}

// ------------------------------------------------------------------
// One warp per node: CSR gather-accumulate + self loop, then bias + LayerNorm
// + ReLU fused, write to g_h.
__global__ __launch_bounds__(256) void k_agg(const float* __restrict__ hw,
                                             const float* __restrict__ bias,
                                             const float* __restrict__ gamma,
                                             const float* __restrict__ beta, int n) {
    int node = (blockIdx.x * blockDim.x + threadIdx.x) >> 5;
    int lane = threadIdx.x & 31;
    if (node >= n) return;
    const float4* hv = (const float4*)hw;
    float di = g_dinv[node];
    float4 sv = hv[(size_t)node * 32 + lane];
    float ax = di * sv.x, ay = di * sv.y, az = di * sv.z, aw = di * sv.w;

    int e = g_rowptr[node], end = g_rowptr[node + 1];
    for (; e + 4 <= end; e += 4) {
        int s0 = g_csr[e], s1 = g_csr[e + 1], s2 = g_csr[e + 2], s3 = g_csr[e + 3];
        float w0 = g_dinv[s0], w1 = g_dinv[s1], w2 = g_dinv[s2], w3 = g_dinv[s3];
        float4 v0 = hv[(size_t)s0 * 32 + lane];
        float4 v1 = hv[(size_t)s1 * 32 + lane];
        float4 v2 = hv[(size_t)s2 * 32 + lane];
        float4 v3 = hv[(size_t)s3 * 32 + lane];
        ax = fmaf(w0, v0.x, ax); ay = fmaf(w0, v0.y, ay); az = fmaf(w0, v0.z, az); aw = fmaf(w0, v0.w, aw);
        ax = fmaf(w1, v1.x, ax); ay = fmaf(w1, v1.y, ay); az = fmaf(w1, v1.z, az); aw = fmaf(w1, v1.w, aw);
        ax = fmaf(w2, v2.x, ax); ay = fmaf(w2, v2.y, ay); az = fmaf(w2, v2.z, az); aw = fmaf(w2, v2.w, aw);
        ax = fmaf(w3, v3.x, ax); ay = fmaf(w3, v3.y, ay); az = fmaf(w3, v3.z, az); aw = fmaf(w3, v3.w, aw);
    }
    for (; e < end; e++) {
        int s = g_csr[e];
        float w = g_dinv[s];
        float4 v = hv[(size_t)s * 32 + lane];
        ax = fmaf(w, v.x, ax); ay = fmaf(w, v.y, ay); az = fmaf(w, v.z, az); aw = fmaf(w, v.w, aw);
    }
    float4 bb = ((const float4*)bias)[lane];
    ax = fmaf(ax, di, bb.x); ay = fmaf(ay, di, bb.y);
    az = fmaf(az, di, bb.z); aw = fmaf(aw, di, bb.w);

    // LayerNorm over 128 via warp reduce
    float s = ax + ay + az + aw;
#pragma unroll
    for (int o = 16; o; o >>= 1) s += __shfl_xor_sync(0xffffffffu, s, o);
    float mean = s * (1.0f / 128.0f);
    float cx = ax - mean, cy = ay - mean, cz = az - mean, cw = aw - mean;
    float v2 = cx * cx + cy * cy + cz * cz + cw * cw;
#pragma unroll
    for (int o = 16; o; o >>= 1) v2 += __shfl_xor_sync(0xffffffffu, v2, o);
    float inv = rsqrtf(v2 * (1.0f / 128.0f) + 1e-5f);
    float4 gg = ((const float4*)gamma)[lane];
    float4 be = ((const float4*)beta)[lane];
    float ox = fmaxf(fmaf(gg.x * cx, inv, be.x), 0.0f);
    float oy = fmaxf(fmaf(gg.y * cy, inv, be.y), 0.0f);
    float oz = fmaxf(fmaf(gg.z * cz, inv, be.z), 0.0f);
    float ow = fmaxf(fmaf(gg.w * cw, inv, be.w), 0.0f);
    ((float4*)g_h)[(size_t)node * 32 + lane] = make_float4(ox, oy, oz, ow);
}

// ------------------------------------------------------------------
// Pooling: warp handles CHUNK consecutive nodes; batch is sorted, so flush
// atomics only on graph-id change.
#define PCHUNK 50
__global__ __launch_bounds__(256) void k_pool(const int* __restrict__ batch, int n) {
    int warp = (blockIdx.x * blockDim.x + threadIdx.x) >> 5;
    int lane = threadIdx.x & 31;
    int beg = warp * PCHUNK;
    if (beg >= n) return;
    int end = beg + PCHUNK; if (end > n) end = n;
    const float4* hv = (const float4*)g_h;
    float ax = 0.f, ay = 0.f, az = 0.f, aw = 0.f;
    int cur = batch[beg];
    for (int i = beg; i < end; i++) {
        int b = batch[i];
        if (b != cur) {
            float* p = g_pool + (size_t)cur * D + lane * 4;
            atomicAdd(p + 0, ax); atomicAdd(p + 1, ay);
            atomicAdd(p + 2, az); atomicAdd(p + 3, aw);
            ax = ay = az = aw = 0.f;
            cur = b;
        }
        float4 v = hv[(size_t)i * 32 + lane];
        ax += v.x; ay += v.y; az += v.z; aw += v.w;
    }
    float* p = g_pool + (size_t)cur * D + lane * 4;
    atomicAdd(p + 0, ax); atomicAdd(p + 1, ay);
    atomicAdd(p + 2, az); atomicAdd(p + 3, aw);
}

__device__ __forceinline__ int lower_bound(const int* a, int n, int v) {
    int lo = 0, hi = n;
    while (lo < hi) { int m = (lo + hi) >> 1; if (a[m] < v) lo = m + 1; else hi = m; }
    return lo;
}

__global__ void k_final(const int* __restrict__ batch, int n, int g, float* __restrict__ out) {
    int i = blockIdx.x * blockDim.x + threadIdx.x;
    if (i >= g * D) return;
    int gi = i / D;
    int cnt = lower_bound(batch, n, gi + 1) - lower_bound(batch, n, gi);
    float c = (float)cnt;
    out[i] = g_pool[i] / fmaxf(c, 1.0f);
}

// ------------------------------------------------------------------
extern "C" void kernel_launch(void* const* d_in, const int* in_sizes, int n_in,
                              void* d_out, int out_size) {
    const float* x      = (const float*)d_in[0];
    const int*   ei     = (const int*)d_in[1];
    const int*   batch  = (const int*)d_in[2];
    const float* Ws     = (const float*)d_in[3];
    const float* bs     = (const float*)d_in[4];
    const float* gammas = (const float*)d_in[5];
    const float* betas  = (const float*)d_in[6];
    float* out = (float*)d_out;

    const int n = in_sizes[0] / D;
    const int e = in_sizes[1] / 2;
    const int L = in_sizes[3] / (D * D);
    const int g = out_size / D;
    const int* src = ei;
    const int* dst = ei + e;

    float* hptr = nullptr;
    float* hwptr = nullptr;
    cudaGetSymbolAddress((void**)&hptr, g_h);
    cudaGetSymbolAddress((void**)&hwptr, g_hw);

    int initN = n > g * D ? n : g * D;
    k_init<<<(initN + 255) / 256, 256>>>(n, g * D);
    k_count<<<(e + 255) / 256, 256>>>(dst, e);
    k_dinv<<<(n + 255) / 256, 256>>>(n);

    int nb = (n + 255) / 256;
    k_scan1<<<nb, 256>>>(n);
    k_scan2<<<1, 256>>>(n, nb);
    k_scan3<<<nb, 256>>>(n);

    k_fill<<<(e + 255) / 256, 256>>>(src, dst, e);

    for (int l = 0; l < L; l++) {
        const float* A = (l == 0) ? x : hptr;
        k_gemm<<<(n + 127) / 128, 256>>>(A, Ws + (size_t)l * D * D, hwptr, n);
        k_agg<<<((n * 32) + 255) / 256, 256>>>(hwptr, bs + (size_t)l * D,
                                               gammas + (size_t)l * D,
                                               betas + (size_t)l * D, n);
    }

    int pwarps = (n + PCHUNK - 1) / PCHUNK;
    k_pool<<<((pwarps * 32) + 255) / 256, 256>>>(batch, n);
    k_final<<<(g * D + 255) / 256, 256>>>(batch, n, g, out);
}

// round 5
// speedup vs baseline: 1.1910x; 1.0845x over previous
#include <cuda_runtime.h>
#include <cuda_bf16.h>
#include <math.h>
#include <cstdint>

#define D 128
#define NMAX 50048
#define EMAX 800000
#define GMAX 64
#define LMAX 4

// ---- scratch (static device globals; no runtime allocation) ----
__device__ float g_dinv[NMAX];
__device__ int   g_deg[NMAX];
__device__ int   g_rowptr[NMAX + 1];
__device__ int   g_cursor[NMAX];
__device__ int   g_csr[EMAX];
__device__ int   g_bsum[256];
__device__ int   g_boff[256];
__device__ float g_hw[NMAX * D];   // GEMM output (pre-aggregation)
__device__ float g_h[NMAX * D];    // layer output
__device__ float g_pool[GMAX * D];
__device__ __nv_bfloat16 g_wt_hi[LMAX * D * D];  // W^T hi, [n][k] row-major
__device__ __nv_bfloat16 g_wt_lo[LMAX * D * D];  // W^T lo

// ------------------------------------------------------------------
__global__ void k_init(int n, int gtot) {
    int i = blockIdx.x * blockDim.x + threadIdx.x;
    if (i < n) { g_deg[i] = 0; g_cursor[i] = 0; }
    if (i < gtot) g_pool[i] = 0.0f;
}

__global__ void k_count(const int* __restrict__ dst, int e) {
    int i = blockIdx.x * blockDim.x + threadIdx.x;
    if (i < e) atomicAdd(&g_deg[dst[i]], 1);
}

__global__ void k_dinv(int n) {
    int i = blockIdx.x * blockDim.x + threadIdx.x;
    if (i < n) g_dinv[i] = rsqrtf((float)(g_deg[i] + 1));  // +1 self loop
}

// W^T hi/lo prep: Ws[l][k][n] fp32 -> g_wt_*[l][n][k] bf16
__global__ void k_wprep(const float* __restrict__ Ws, int L) {
    int i = blockIdx.x * blockDim.x + threadIdx.x;
    if (i >= L * D * D) return;
    int l = i >> 14, r = i & 16383;
    int k = r >> 7, nn = r & 127;
    float w = Ws[i];
    __nv_bfloat16 hi = __float2bfloat16_rn(w);
    __nv_bfloat16 lo = __float2bfloat16_rn(w - __bfloat162float(hi));
    g_wt_hi[(l << 14) + nn * D + k] = hi;
    g_wt_lo[(l << 14) + nn * D + k] = lo;
}

// ---- multi-block exclusive scan of g_deg -> g_rowptr ----
__global__ void k_scan1(int n) {
    __shared__ int sh[256];
    const int t = threadIdx.x;
    const int i = blockIdx.x * 256 + t;
    int v = (i < n) ? g_deg[i] : 0;
    sh[t] = v;
    __syncthreads();
#pragma unroll
    for (int o = 1; o < 256; o <<= 1) {
        int u = (t >= o) ? sh[t - o] : 0;
        __syncthreads();
        sh[t] += u;
        __syncthreads();
    }
    if (i < n) g_rowptr[i] = sh[t] - v;
    if (t == 255) g_bsum[blockIdx.x] = sh[255];
}

__global__ void k_scan2(int n, int nb) {
    __shared__ int sh[256];
    const int t = threadIdx.x;
    int v = (t < nb) ? g_bsum[t] : 0;
    sh[t] = v;
    __syncthreads();
#pragma unroll
    for (int o = 1; o < 256; o <<= 1) {
        int u = (t >= o) ? sh[t - o] : 0;
        __syncthreads();
        sh[t] += u;
        __syncthreads();
    }
    g_boff[t] = sh[t] - v;
    if (t == 255) g_rowptr[n] = sh[255];
}

__global__ void k_scan3(int n) {
    const int i = blockIdx.x * 256 + threadIdx.x;
    if (i < n) g_rowptr[i] += g_boff[blockIdx.x];
}

__global__ void k_fill(const int* __restrict__ src, const int* __restrict__ dst, int e) {
    int i = blockIdx.x * blockDim.x + threadIdx.x;
    if (i < e) {
        int d = dst[i];
        int p = atomicAdd(&g_cursor[d], 1);
        g_csr[g_rowptr[d] + p] = src[i];
    }
}

// ------------------------------------------------------------------
// Tensor-core GEMM via mma.sync (bf16 hi/lo split, fp32 accumulate).
// C[n,128] = A[n,128] @ W[128,128]; B operands pre-split W^T [n][k] bf16.
// Block: 128 rows, 8 warps in 4x2 grid; warp tile 32x64; no smem.

__device__ __forceinline__ void mma16816(float* c, uint32_t a0, uint32_t a1,
                                         uint32_t a2, uint32_t a3,
                                         uint32_t b0, uint32_t b1) {
    asm volatile(
        "mma.sync.aligned.m16n8k16.row.col.f32.bf16.bf16.f32 "
        "{%0,%1,%2,%3}, {%4,%5,%6,%7}, {%8,%9}, {%0,%1,%2,%3};"
        : "+f"(c[0]), "+f"(c[1]), "+f"(c[2]), "+f"(c[3])
        : "r"(a0), "r"(a1), "r"(a2), "r"(a3), "r"(b0), "r"(b1));
}

__device__ __forceinline__ uint32_t pack_hi(float2 p) {
    __nv_bfloat162 h = __float22bfloat162_rn(p);
    return *reinterpret_cast<uint32_t*>(&h);
}
__device__ __forceinline__ uint32_t pack_lo(float2 p, uint32_t hibits) {
    __nv_bfloat162 h = *reinterpret_cast<__nv_bfloat162*>(&hibits);
    float2 r = make_float2(p.x - __bfloat162float(h.x), p.y - __bfloat162float(h.y));
    __nv_bfloat162 l = __float22bfloat162_rn(r);
    return *reinterpret_cast<uint32_t*>(&l);
}

__global__ __launch_bounds__(256) void k_gemm_mma(const float* __restrict__ A,
                                                  const __nv_bfloat16* __restrict__ Bh,
                                                  const __nv_bfloat16* __restrict__ Bl,
                                                  float* __restrict__ C, int n) {
    const int tid = threadIdx.x;
    const int lane = tid & 31;
    const int wid = tid >> 5;
    const int wr = wid >> 1;      // 0..3
    const int wc = wid & 1;       // 0..1
    const int gid = lane >> 2;    // 0..7
    const int tig = lane & 3;     // 0..3
    const int rowbase = blockIdx.x * 128 + wr * 32;
    const int colbase = wc * 64;

    float acc[2][8][4];
#pragma unroll
    for (int mt = 0; mt < 2; mt++)
#pragma unroll
        for (int nt = 0; nt < 8; nt++)
#pragma unroll
            for (int q = 0; q < 4; q++) acc[mt][nt][q] = 0.0f;

    const float2 z2 = make_float2(0.f, 0.f);

    for (int k0 = 0; k0 < 128; k0 += 16) {
        uint32_t ah[2][4], al[2][4];
#pragma unroll
        for (int mt = 0; mt < 2; mt++) {
            int r0 = rowbase + mt * 16 + gid;
            int r1 = r0 + 8;
            int kc = k0 + tig * 2;
            const float2* p0 = (const float2*)(A + (size_t)r0 * 128 + kc);
            const float2* p1 = (const float2*)(A + (size_t)r1 * 128 + kc);
            float2 f00 = (r0 < n) ? p0[0] : z2;   // (r0, kc..kc+1)
            float2 f01 = (r0 < n) ? p0[4] : z2;   // (r0, kc+8..kc+9)
            float2 f10 = (r1 < n) ? p1[0] : z2;
            float2 f11 = (r1 < n) ? p1[4] : z2;
            ah[mt][0] = pack_hi(f00); al[mt][0] = pack_lo(f00, ah[mt][0]);
            ah[mt][1] = pack_hi(f10); al[mt][1] = pack_lo(f10, ah[mt][1]);
            ah[mt][2] = pack_hi(f01); al[mt][2] = pack_lo(f01, ah[mt][2]);
            ah[mt][3] = pack_hi(f11); al[mt][3] = pack_lo(f11, ah[mt][3]);
        }
#pragma unroll
        for (int nt = 0; nt < 8; nt++) {
            int nn = colbase + nt * 8 + gid;
            const uint32_t* bhp = (const uint32_t*)(Bh + (size_t)nn * 128 + k0 + tig * 2);
            const uint32_t* blp = (const uint32_t*)(Bl + (size_t)nn * 128 + k0 + tig * 2);
            uint32_t bh0 = bhp[0], bh1 = bhp[4];
            uint32_t bl0 = blp[0], bl1 = blp[4];
#pragma unroll
            for (int mt = 0; mt < 2; mt++) {
                mma16816(acc[mt][nt], ah[mt][0], ah[mt][1], ah[mt][2], ah[mt][3], bh0, bh1);
                mma16816(acc[mt][nt], al[mt][0], al[mt][1], al[mt][2], al[mt][3], bh0, bh1);
                mma16816(acc[mt][nt], ah[mt][0], ah[mt][1], ah[mt][2], ah[mt][3], bl0, bl1);
            }
        }
    }

    // epilogue
#pragma unroll
    for (int mt = 0; mt < 2; mt++) {
        int r0 = rowbase + mt * 16 + gid;
        int r1 = r0 + 8;
#pragma unroll
        for (int nt = 0; nt < 8; nt++) {
            int cc = colbase + nt * 8 + tig * 2;
            if (r0 < n)
                *(float2*)(C + (size_t)r0 * 128 + cc) = make_float2(acc[mt][nt][0], acc[mt][nt][1]);
            if (r1 < n)
                *(float2*)(C + (size_t)r1 * 128 + cc) = make_float2(acc[mt][nt][2], acc[mt][nt][3]);
        }
    }
}

// ------------------------------------------------------------------
// One warp per node: CSR gather-accumulate + self loop, then bias + LayerNorm
// + ReLU fused, write to g_h.
__global__ __launch_bounds__(256) void k_agg(const float* __restrict__ hw,
                                             const float* __restrict__ bias,
                                             const float* __restrict__ gamma,
                                             const float* __restrict__ beta, int n) {
    int node = (blockIdx.x * blockDim.x + threadIdx.x) >> 5;
    int lane = threadIdx.x & 31;
    if (node >= n) return;
    const float4* hv = (const float4*)hw;
    float di = g_dinv[node];
    float4 sv = hv[(size_t)node * 32 + lane];
    float ax = di * sv.x, ay = di * sv.y, az = di * sv.z, aw = di * sv.w;

    int e = g_rowptr[node], end = g_rowptr[node + 1];
    for (; e + 4 <= end; e += 4) {
        int s0 = g_csr[e], s1 = g_csr[e + 1], s2 = g_csr[e + 2], s3 = g_csr[e + 3];
        float w0 = g_dinv[s0], w1 = g_dinv[s1], w2 = g_dinv[s2], w3 = g_dinv[s3];
        float4 v0 = hv[(size_t)s0 * 32 + lane];
        float4 v1 = hv[(size_t)s1 * 32 + lane];
        float4 v2 = hv[(size_t)s2 * 32 + lane];
        float4 v3 = hv[(size_t)s3 * 32 + lane];
        ax = fmaf(w0, v0.x, ax); ay = fmaf(w0, v0.y, ay); az = fmaf(w0, v0.z, az); aw = fmaf(w0, v0.w, aw);
        ax = fmaf(w1, v1.x, ax); ay = fmaf(w1, v1.y, ay); az = fmaf(w1, v1.z, az); aw = fmaf(w1, v1.w, aw);
        ax = fmaf(w2, v2.x, ax); ay = fmaf(w2, v2.y, ay); az = fmaf(w2, v2.z, az); aw = fmaf(w2, v2.w, aw);
        ax = fmaf(w3, v3.x, ax); ay = fmaf(w3, v3.y, ay); az = fmaf(w3, v3.z, az); aw = fmaf(w3, v3.w, aw);
    }
    for (; e < end; e++) {
        int s = g_csr[e];
        float w = g_dinv[s];
        float4 v = hv[(size_t)s * 32 + lane];
        ax = fmaf(w, v.x, ax); ay = fmaf(w, v.y, ay); az = fmaf(w, v.z, az); aw = fmaf(w, v.w, aw);
    }
    float4 bb = ((const float4*)bias)[lane];
    ax = fmaf(ax, di, bb.x); ay = fmaf(ay, di, bb.y);
    az = fmaf(az, di, bb.z); aw = fmaf(aw, di, bb.w);

    // LayerNorm over 128 via warp reduce
    float s = ax + ay + az + aw;
#pragma unroll
    for (int o = 16; o; o >>= 1) s += __shfl_xor_sync(0xffffffffu, s, o);
    float mean = s * (1.0f / 128.0f);
    float cx = ax - mean, cy = ay - mean, cz = az - mean, cw = aw - mean;
    float v2 = cx * cx + cy * cy + cz * cz + cw * cw;
#pragma unroll
    for (int o = 16; o; o >>= 1) v2 += __shfl_xor_sync(0xffffffffu, v2, o);
    float inv = rsqrtf(v2 * (1.0f / 128.0f) + 1e-5f);
    float4 gg = ((const float4*)gamma)[lane];
    float4 be = ((const float4*)beta)[lane];
    float ox = fmaxf(fmaf(gg.x * cx, inv, be.x), 0.0f);
    float oy = fmaxf(fmaf(gg.y * cy, inv, be.y), 0.0f);
    float oz = fmaxf(fmaf(gg.z * cz, inv, be.z), 0.0f);
    float ow = fmaxf(fmaf(gg.w * cw, inv, be.w), 0.0f);
    ((float4*)g_h)[(size_t)node * 32 + lane] = make_float4(ox, oy, oz, ow);
}

// ------------------------------------------------------------------
#define PCHUNK 50
__global__ __launch_bounds__(256) void k_pool(const int* __restrict__ batch, int n) {
    int warp = (blockIdx.x * blockDim.x + threadIdx.x) >> 5;
    int lane = threadIdx.x & 31;
    int beg = warp * PCHUNK;
    if (beg >= n) return;
    int end = beg + PCHUNK; if (end > n) end = n;
    const float4* hv = (const float4*)g_h;
    float ax = 0.f, ay = 0.f, az = 0.f, aw = 0.f;
    int cur = batch[beg];
    for (int i = beg; i < end; i++) {
        int b = batch[i];
        if (b != cur) {
            float* p = g_pool + (size_t)cur * D + lane * 4;
            atomicAdd(p + 0, ax); atomicAdd(p + 1, ay);
            atomicAdd(p + 2, az); atomicAdd(p + 3, aw);
            ax = ay = az = aw = 0.f;
            cur = b;
        }
        float4 v = hv[(size_t)i * 32 + lane];
        ax += v.x; ay += v.y; az += v.z; aw += v.w;
    }
    float* p = g_pool + (size_t)cur * D + lane * 4;
    atomicAdd(p + 0, ax); atomicAdd(p + 1, ay);
    atomicAdd(p + 2, az); atomicAdd(p + 3, aw);
}

__device__ __forceinline__ int lower_bound(const int* a, int n, int v) {
    int lo = 0, hi = n;
    while (lo < hi) { int m = (lo + hi) >> 1; if (a[m] < v) lo = m + 1; else hi = m; }
    return lo;
}

__global__ void k_final(const int* __restrict__ batch, int n, int g, float* __restrict__ out) {
    int i = blockIdx.x * blockDim.x + threadIdx.x;
    if (i >= g * D) return;
    int gi = i / D;
    int cnt = lower_bound(batch, n, gi + 1) - lower_bound(batch, n, gi);
    float c = (float)cnt;
    out[i] = g_pool[i] / fmaxf(c, 1.0f);
}

// ------------------------------------------------------------------
extern "C" void kernel_launch(void* const* d_in, const int* in_sizes, int n_in,
                              void* d_out, int out_size) {
    const float* x      = (const float*)d_in[0];
    const int*   ei     = (const int*)d_in[1];
    const int*   batch  = (const int*)d_in[2];
    const float* Ws     = (const float*)d_in[3];
    const float* bs     = (const float*)d_in[4];
    const float* gammas = (const float*)d_in[5];
    const float* betas  = (const float*)d_in[6];
    float* out = (float*)d_out;

    const int n = in_sizes[0] / D;
    const int e = in_sizes[1] / 2;
    const int L = in_sizes[3] / (D * D);
    const int g = out_size / D;
    const int* src = ei;
    const int* dst = ei + e;

    float* hptr = nullptr;
    float* hwptr = nullptr;
    __nv_bfloat16* whptr = nullptr;
    __nv_bfloat16* wlptr = nullptr;
    cudaGetSymbolAddress((void**)&hptr, g_h);
    cudaGetSymbolAddress((void**)&hwptr, g_hw);
    cudaGetSymbolAddress((void**)&whptr, g_wt_hi);
    cudaGetSymbolAddress((void**)&wlptr, g_wt_lo);

    const int gemm_blocks = (n + 127) / 128;

    int initN = n > g * D ? n : g * D;
    k_init<<<(initN + 255) / 256, 256>>>(n, g * D);                 // 0
    k_count<<<(e + 255) / 256, 256>>>(dst, e);                      // 1
    k_wprep<<<(L * D * D + 255) / 256, 256>>>(Ws, L);               // 2
    k_dinv<<<(n + 255) / 256, 256>>>(n);                            // 3
    int nb = (n + 255) / 256;
    k_scan1<<<nb, 256>>>(n);                                        // 4
    // layer 0 GEMM early (independent of CSR) -> profiled at skip=5
    k_gemm_mma<<<gemm_blocks, 256>>>(x, whptr, wlptr, hwptr, n);    // 5
    k_scan2<<<1, 256>>>(n, nb);                                     // 6
    k_scan3<<<nb, 256>>>(n);                                        // 7
    k_fill<<<(e + 255) / 256, 256>>>(src, dst, e);                  // 8

    for (int l = 0; l < L; l++) {
        if (l > 0)
            k_gemm_mma<<<gemm_blocks, 256>>>(hptr, whptr + (size_t)l * D * D,
                                             wlptr + (size_t)l * D * D, hwptr, n);
        k_agg<<<((n * 32) + 255) / 256, 256>>>(hwptr, bs + (size_t)l * D,
                                               gammas + (size_t)l * D,
                                               betas + (size_t)l * D, n);
    }

    int pwarps = (n + PCHUNK - 1) / PCHUNK;
    k_pool<<<((pwarps * 32) + 255) / 256, 256>>>(batch, n);
    k_final<<<(g * D + 255) / 256, 256>>>(batch, n, g, out);
}